// round 4
// baseline (speedup 1.0000x reference)
#include <cuda_runtime.h>
#include <math.h>

#define T_BUCKETS 8192
#define HIST_BLOCKS 1184
#define HIST_THREADS 256
#define FIN_THREADS 1024

// Per-bucket accumulator in global (L2-resident: 128 KB):
//   acc[t] = { sum exp(p), sum p, count, observed-count }   (all float, exact where needed)
__device__ float4 g_acc[T_BUCKETS];

// ---------------------------------------------------------------------------
// Kernel 0: zero the accumulator (must run EVERY launch: __device__ globals
// persist across graph replays).
// ---------------------------------------------------------------------------
__global__ void zero_kernel() {
    int i = blockIdx.x * blockDim.x + threadIdx.x;
    if (i < T_BUCKETS) g_acc[i] = make_float4(0.f, 0.f, 0.f, 0.f);
}

// ---------------------------------------------------------------------------
// Kernel 1: streaming pass, ONE red.global.add.v4.f32 per element.
// ---------------------------------------------------------------------------
__device__ __forceinline__ void red_v4(float4* addr, float e, float p, float o) {
    asm volatile("red.global.add.v4.f32 [%0], {%1, %2, %3, %4};"
                 :: "l"(addr), "f"(e), "f"(p), "f"(1.0f), "f"(o)
                 : "memory");
}

__global__ __launch_bounds__(HIST_THREADS)
void hist_kernel(const float* __restrict__ preds,
                 const int*   __restrict__ times,
                 const int*   __restrict__ obsv,
                 int n) {
    const int n4 = n >> 2;
    const float4* p4 = (const float4*)preds;
    const int4*   t4 = (const int4*)times;
    const int4*   o4 = (const int4*)obsv;

    for (int i = blockIdx.x * HIST_THREADS + threadIdx.x; i < n4;
         i += gridDim.x * HIST_THREADS) {
        float4 p = p4[i];
        int4   t = t4[i];
        int4   o = o4[i];
        red_v4(&g_acc[t.x], expf(p.x), p.x, o.x ? 1.0f : 0.0f);
        red_v4(&g_acc[t.y], expf(p.y), p.y, o.y ? 1.0f : 0.0f);
        red_v4(&g_acc[t.z], expf(p.z), p.z, o.z ? 1.0f : 0.0f);
        red_v4(&g_acc[t.w], expf(p.w), p.w, o.w ? 1.0f : 0.0f);
    }

    // tail (n % 4) — handled once by block 0
    if (blockIdx.x == 0) {
        for (int i = (n4 << 2) + threadIdx.x; i < n; i += HIST_THREADS) {
            float p = preds[i];
            red_v4(&g_acc[times[i]], expf(p), p, obsv[i] ? 1.0f : 0.0f);
        }
    }
}

// ---------------------------------------------------------------------------
// Kernel 2: single block. Double-precision suffix scan over buckets gives
// R[t] = sum_{t'>=t} S[t']. Efron tied-term closed form per bucket:
//   sum_{l=0}^{m-1} log(R - (l/m)S) = m*log(a) + lgamma(x+1) - lgamma(x+1-m),
//   a = S/m, x = R/a (>= m).
//   ll = sum_t obs_t * ( P_t - efron_t );  out = -ll.
// ---------------------------------------------------------------------------
__global__ __launch_bounds__(FIN_THREADS, 1)
void final_kernel(float* __restrict__ out) {
    __shared__ double sbuf[FIN_THREADS];
    const int tid = threadIdx.x;

    // each thread owns 8 consecutive buckets
    double S[8], P[8];
    int    M[8], O[8];
    double chunk = 0.0;
    #pragma unroll
    for (int k = 0; k < 8; k++) {
        float4 a = g_acc[tid * 8 + k];
        S[k] = (double)a.x;
        P[k] = (double)a.y;
        M[k] = (int)a.z;
        O[k] = (a.w > 0.0f) ? 1 : 0;
        chunk += S[k];
    }

    // inclusive suffix scan of per-thread chunk sums (Hillis–Steele)
    sbuf[tid] = chunk;
    __syncthreads();
    for (int off = 1; off < FIN_THREADS; off <<= 1) {
        double add = (tid + off < FIN_THREADS) ? sbuf[tid + off] : 0.0;
        __syncthreads();
        sbuf[tid] += add;
        __syncthreads();
    }
    double run = sbuf[tid] - chunk;  // exclusive suffix (chunks after mine)

    double contrib = 0.0;
    #pragma unroll
    for (int k = 7; k >= 0; k--) {
        run += S[k];                 // run = R[bucket]
        if (M[k] > 0 && O[k]) {
            double m = (double)M[k];
            double a = S[k] / m;
            double x = run / a;      // >= m
            double efron = m * log(a) + lgamma(x + 1.0) - lgamma(x + 1.0 - m);
            contrib += P[k] - efron;
        }
    }

    __syncthreads();
    sbuf[tid] = contrib;
    __syncthreads();
    for (int off = FIN_THREADS / 2; off > 0; off >>= 1) {
        if (tid < off) sbuf[tid] += sbuf[tid + off];
        __syncthreads();
    }
    if (tid == 0) out[0] = (float)(-sbuf[0]);
}

// ---------------------------------------------------------------------------
extern "C" void kernel_launch(void* const* d_in, const int* in_sizes, int n_in,
                              void* d_out, int out_size) {
    const float* preds = (const float*)d_in[0];
    const int*   times = (const int*)d_in[1];
    const int*   obsv  = (const int*)d_in[2];
    int n = in_sizes[0];

    zero_kernel<<<(T_BUCKETS + 255) / 256, 256>>>();
    hist_kernel<<<HIST_BLOCKS, HIST_THREADS>>>(preds, times, obsv, n);
    final_kernel<<<1, FIN_THREADS>>>((float*)d_out);
}